// round 2
// baseline (speedup 1.0000x reference)
#include <cuda_runtime.h>
#include <cstdint>

// Problem constants
#define BB 8
#define CC 3
#define HH 512
#define WW 512
#define KK 8

// Output layout (float32, concatenated in reference-return order):
//   best_warped [B,C,H,W], best_idx [B], best_mse [B],
//   all_warped  [B,K,C,H,W], all_mse [B,K], flows [K,H,W,2]
static constexpr size_t N_BW      = (size_t)BB * CC * HH * WW;          // 6,291,456
static constexpr size_t OFF_BW    = 0;
static constexpr size_t OFF_IDX   = N_BW;                               // +8
static constexpr size_t OFF_BMSE  = OFF_IDX + BB;                       // +8
static constexpr size_t OFF_AW    = OFF_BMSE + BB;
static constexpr size_t N_AW      = (size_t)BB * KK * CC * HH * WW;     // 50,331,648
static constexpr size_t OFF_AMSE  = OFF_AW + N_AW;                      // +64
static constexpr size_t OFF_FLOWS = OFF_AMSE + (size_t)BB * KK;

// Scratch (no allocations allowed)
__device__ double g_mse[BB * KK];
__device__ int    g_best[BB];
__device__ float  g_dx[KK * HH];   // dx[k][y] = u_top[k]*exp(-decay_y[k]*y/(H-1))
__device__ float  g_dy[KK * WW];   // dy[k][x] = v_left[k]*exp(-decay_x[k]*x/(W-1))

__device__ __forceinline__ float softplusf(float v) {
    return v > 20.f ? v : log1pf(expf(v));
}

// ---------------------------------------------------------------------------
// Kernel 1: per-class params -> separable flow tables; zero MSE accumulators.
// grid = 16 blocks x 512 threads (covers K*H + K*W = 8192 entries).
// ---------------------------------------------------------------------------
__global__ void prep_kernel(const float* __restrict__ cp) {
    __shared__ float su[KK], sv[KK], sdecx[KK], sdecy[KK];
    int tid = threadIdx.x;
    if (tid < KK) {
        float p0 = cp[4 * tid + 0];
        float p1 = cp[4 * tid + 1];
        float p2 = cp[4 * tid + 2];
        float p3 = cp[4 * tid + 3];
        sv[tid]    = 0.5f * tanhf(p0);   // v_left  (MAX_SHIFT = 0.5)
        su[tid]    = 0.5f * tanhf(p1);   // u_top
        sdecx[tid] = softplusf(p2);      // decay_x
        sdecy[tid] = softplusf(p3);      // decay_y
    }
    __syncthreads();
    int g = blockIdx.x * 512 + tid;
    const float inv = 1.0f / 511.0f;
    if (g < KK * HH) {
        int k = g >> 9, y = g & 511;
        g_dx[g] = su[k] * expf(-sdecy[k] * ((float)y * inv));
    } else {
        int g2 = g - KK * HH;
        int k = g2 >> 9, x = g2 & 511;
        g_dy[g2] = sv[k] * expf(-sdecx[k] * ((float)x * inv));
    }
    if (blockIdx.x == 0 && tid < BB * KK) g_mse[tid] = 0.0;
}

// ---------------------------------------------------------------------------
// Kernel 2: flows output [K,H,W,2] = {dx[k,y], dy[k,x]}.  grid = K*H x 512.
// Streaming stores: write-once data, keep it out of L2.
// ---------------------------------------------------------------------------
__global__ void flows_kernel(float* __restrict__ out) {
    int bid = blockIdx.x;            // k*H + y
    int k = bid >> 9;
    int x = threadIdx.x;
    float dx = g_dx[bid];
    float dy = g_dy[(k << 9) + x];
    float2* f = reinterpret_cast<float2*>(out + OFF_FLOWS);
    __stcs(&f[((size_t)bid << 9) + x], make_float2(dx, dy));
}

// ---------------------------------------------------------------------------
// Kernel 3 (hot): warp all K classes for one (b, y) row; write all_warped;
// accumulate per-(b,k) squared error. grid = B*H x 512 threads.
// ---------------------------------------------------------------------------
__global__ void __launch_bounds__(512)
warp_mse_kernel(const float* __restrict__ pred, const float* __restrict__ gt,
                float* __restrict__ out) {
    __shared__ float sp[CC][3][WW];     // 3 rows (y-1, y, y+1 clamped) x 3 channels
    __shared__ float sdy[KK][WW];
    __shared__ float sred[16][KK];

    int bid = blockIdx.x;
    int b = bid >> 9;
    int y = bid & 511;
    int x = threadIdx.x;

    int ym1 = max(y - 1, 0);
    int yp1 = min(y + 1, HH - 1);
#pragma unroll
    for (int c = 0; c < CC; c++) {
        const float* base = pred + (size_t)(b * CC + c) * HH * WW;
        sp[c][0][x] = __ldg(&base[(size_t)ym1 * WW + x]);
        sp[c][1][x] = __ldg(&base[(size_t)y   * WW + x]);
        sp[c][2][x] = __ldg(&base[(size_t)yp1 * WW + x]);
    }
#pragma unroll
    for (int k = 0; k < KK; k++) sdy[k][x] = g_dy[(k << 9) + x];

    float gr[CC];
#pragma unroll
    for (int c = 0; c < CC; c++)
        gr[c] = __ldg(&gt[((size_t)(b * CC + c) * HH + y) * WW + x]);
    __syncthreads();

    float acc[KK];
    const float fx = (float)x;
    const float fy = (float)y;
#pragma unroll
    for (int k = 0; k < KK; k++) {
        float dxk = g_dx[(k << 9) + y];                       // uniform per block
        float ix = fminf(fmaxf(fx + dxk,      0.f), 511.f);
        float iy = fminf(fmaxf(fy + sdy[k][x], 0.f), 511.f);
        float x0f = floorf(ix), y0f = floorf(iy);
        float wx = ix - x0f, wy = iy - y0f;
        int x0 = (int)x0f;
        int x1 = min(x0 + 1, WW - 1);
        int y0 = (int)y0f;
        int r0 = y0 - y + 1;                                  // in {0,1}
        int r1 = min(y0 + 1, HH - 1) - y + 1;                 // in {1,2}
        float w00 = (1.f - wx) * (1.f - wy);
        float w01 = wx * (1.f - wy);
        float w10 = (1.f - wx) * wy;
        float w11 = wx * wy;
        float a = 0.f;
#pragma unroll
        for (int c = 0; c < CC; c++) {
            float v = sp[c][r0][x0] * w00 + sp[c][r0][x1] * w01 +
                      sp[c][r1][x0] * w10 + sp[c][r1][x1] * w11;
            __stcs(&out[OFF_AW + ((((size_t)(b * KK + k)) * CC + c) * HH + y) * WW + x], v);
            float d = v - gr[c];
            a = fmaf(d, d, a);
        }
        acc[k] = a;
    }

    // Block reduction of 8 accumulators, then one double atomic per (b,k).
#pragma unroll
    for (int k = 0; k < KK; k++) {
#pragma unroll
        for (int off = 16; off > 0; off >>= 1)
            acc[k] += __shfl_down_sync(0xffffffffu, acc[k], off);
    }
    int lane = x & 31, warp = x >> 5;
    if (lane == 0) {
#pragma unroll
        for (int k = 0; k < KK; k++) sred[warp][k] = acc[k];
    }
    __syncthreads();
    if (x < KK) {
        double s = 0.0;
#pragma unroll
        for (int w = 0; w < 16; w++) s += (double)sred[w][x];
        atomicAdd(&g_mse[b * KK + x], s);
    }
}

// ---------------------------------------------------------------------------
// Kernel 4: finalize MSEs, argmin per batch. 1 block x 64 threads.
// ---------------------------------------------------------------------------
__global__ void reduce_kernel(float* __restrict__ out) {
    int tid = threadIdx.x;
    const double invN = 1.0 / ((double)CC * HH * WW);
    if (tid < BB * KK)
        out[OFF_AMSE + tid] = (float)(g_mse[tid] * invN);
    __syncthreads();
    if (tid < BB) {
        int b = tid;
        double best = g_mse[b * KK];
        int bi = 0;
#pragma unroll
        for (int k = 1; k < KK; k++) {
            double v = g_mse[b * KK + k];
            if (v < best) { best = v; bi = k; }   // strict < => first min (jnp.argmin)
        }
        g_best[b] = bi;
        out[OFF_IDX  + b] = (float)bi;
        out[OFF_BMSE + b] = (float)(best * invN);
    }
}

// ---------------------------------------------------------------------------
// Kernel 5: best_warped[b] = all_warped[b, best_idx[b]]. grid = B*C*H x 128.
// ---------------------------------------------------------------------------
__global__ void gather_kernel(float* __restrict__ out) {
    int bid = blockIdx.x;
    int b = bid / (CC * HH);
    int rem = bid - b * (CC * HH);
    int c = rem / HH;
    int y = rem - c * HH;
    int idx = g_best[b];
    const float4* src = reinterpret_cast<const float4*>(
        out + OFF_AW + ((((size_t)(b * KK + idx)) * CC + c) * HH + y) * WW);
    float4* dst = reinterpret_cast<float4*>(
        out + OFF_BW + (((size_t)(b * CC + c) * HH + y) * WW));
    dst[threadIdx.x] = __ldcs(&src[threadIdx.x]);
}

// ---------------------------------------------------------------------------
extern "C" void kernel_launch(void* const* d_in, const int* in_sizes, int n_in,
                              void* d_out, int out_size) {
    const float* pred = (const float*)d_in[0];   // [B,C,H,W]
    const float* gt   = (const float*)d_in[1];   // [B,C,H,W]
    const float* cp   = (const float*)d_in[2];   // [K,4]
    float* out = (float*)d_out;

    prep_kernel<<<16, 512>>>(cp);
    flows_kernel<<<KK * HH, 512>>>(out);
    warp_mse_kernel<<<BB * HH, 512>>>(pred, gt, out);
    reduce_kernel<<<1, 64>>>(out);
    gather_kernel<<<BB * CC * HH, 128>>>(out);
}